// round 10
// baseline (speedup 1.0000x reference)
#include <cuda_runtime.h>
#include <cstdint>

#define Bn 4
#define Cn 128
#define Hn 128
#define Wn 128
#define On 256
#define HWn (Hn*Wn)

// Scratch (allocation-free rule: __device__ globals)
__device__ float g_mid[Bn*HWn*Cn];      // depthwise output, [p][c] layout
__device__ float g_xT[Bn*HWn*Cn];       // x transposed to [b][h][w][c]
__device__ float g_om[Bn*32*HWn];       // raw offset-conv output, 32 ch (27 used)
__device__ float g_wk1h[32*9*128];      // offset-conv weights tf32-hi [o][tap][c]
__device__ float g_wk1l[32*9*128];      // offset-conv weights tf32-lo

__device__ __forceinline__ uint32_t f2tf32(float f) {
    uint32_t u;
    asm("cvt.rna.tf32.f32 %0, %1;" : "=r"(u) : "f"(f));
    return u;
}

__device__ __forceinline__ void mma_tf32(float* d,
                                         uint32_t a0, uint32_t a1, uint32_t a2, uint32_t a3,
                                         uint32_t b0, uint32_t b1) {
    asm volatile(
        "mma.sync.aligned.m16n8k8.row.col.f32.tf32.tf32.f32 "
        "{%0,%1,%2,%3}, {%4,%5,%6,%7}, {%8,%9}, {%0,%1,%2,%3};"
        : "+f"(d[0]), "+f"(d[1]), "+f"(d[2]), "+f"(d[3])
        : "r"(a0), "r"(a1), "r"(a2), "r"(a3), "r"(b0), "r"(b1));
}

// ---------------------------------------------------------------------------
// K0: build tf32 hi/lo split of offset-conv weights as [o pad32][tap][c].
// ---------------------------------------------------------------------------
__global__ void k0_wk1(const float* __restrict__ w_off) {
    int idx = blockIdx.x * 256 + threadIdx.x;
    if (idx >= 32*1152) return;
    int o = idx / 1152, r = idx % 1152;      // r = tap*128 + c
    int tap = r >> 7, c = r & 127;
    float v = (o < 27) ? w_off[(o*Cn + c)*9 + tap] : 0.f;
    uint32_t hi = f2tf32(v);
    g_wk1h[idx] = __uint_as_float(hi);
    g_wk1l[idx] = __uint_as_float(f2tf32(v - __uint_as_float(hi)));
}

// ---------------------------------------------------------------------------
// KT: transpose x [b][c][h][w] -> xT [b][hw][c] (channels contiguous).
// ---------------------------------------------------------------------------
__global__ __launch_bounds__(256) void kT(const float* __restrict__ x) {
    __shared__ float t[32][33];
    int b = blockIdx.z;
    int p0 = blockIdx.x * 32, c0 = blockIdx.y * 32;
    int tx = threadIdx.x & 31, ty = threadIdx.x >> 5;  // 32 x 8
    #pragma unroll
    for (int j = 0; j < 4; j++)
        t[ty + j*8][tx] = x[((size_t)b*Cn + c0 + ty + j*8)*HWn + p0 + tx];
    __syncthreads();
    #pragma unroll
    for (int j = 0; j < 4; j++)
        g_xT[((size_t)b*HWn + p0 + ty + j*8)*128 + c0 + tx] = t[tx][ty + j*8];
}

// ---------------------------------------------------------------------------
// K1: offset/mask conv as tf32 mma.sync GEMM with 3-MMA precision split.
// (unchanged)
// ---------------------------------------------------------------------------
#define ROWP 136
#define XSTR 552
#define AP   76
#define K1_SMEM ((16*XSTR + 64*AP) * 4)

__global__ __launch_bounds__(256) void k1_mma(const float* __restrict__ x) {
    extern __shared__ float sm[];
    float* sxh = sm;
    float* sxl = sm + 8*XSTR;
    float* sAh = sm + 16*XSTR;
    float* sAl = sAh + 32*AP;

    int tid = threadIdx.x, wid = tid >> 5, lid = tid & 31;
    int g = lid >> 2, tig = lid & 3;
    int h0 = blockIdx.x * 2, b = blockIdx.y;

    for (int i = tid; i < 16*XSTR; i += 256) sm[i] = 0.f;

    float acc[2][4][4];
    #pragma unroll
    for (int mt = 0; mt < 2; mt++)
        #pragma unroll
        for (int nt = 0; nt < 4; nt++)
            #pragma unroll
            for (int j = 0; j < 4; j++) acc[mt][nt][j] = 0.f;

    int hh  = wid >> 2;
    int wc0 = (wid & 3) * 32;

    int s_cl = tid >> 5;
    int s_r  = (tid >> 3) & 3;
    int s_q  = tid & 7;

    for (int c0 = 0; c0 < Cn; c0 += 8) {
        __syncthreads();
        {
            int row = h0 - 1 + s_r;
            bool ok = (row >= 0) && (row < Hn);
            const float* xp = x + ((size_t)b*Cn + (c0 + s_cl))*HWn + row*Wn;
            float* dh = sxh + s_cl*XSTR + s_r*ROWP + 4;
            float* dl = sxl + s_cl*XSTR + s_r*ROWP + 4;
            #pragma unroll
            for (int j = 0; j < 4; j++) {
                int col = (s_q + 8*j) * 4;
                float4 v = ok ? *(const float4*)(xp + col) : make_float4(0.f,0.f,0.f,0.f);
                uint4 vh = { f2tf32(v.x), f2tf32(v.y), f2tf32(v.z), f2tf32(v.w) };
                uint4 vl = { f2tf32(v.x - __uint_as_float(vh.x)),
                             f2tf32(v.y - __uint_as_float(vh.y)),
                             f2tf32(v.z - __uint_as_float(vh.z)),
                             f2tf32(v.w - __uint_as_float(vh.w)) };
                *(uint4*)(dh + col) = vh;
                *(uint4*)(dl + col) = vl;
            }
        }
        #pragma unroll
        for (int t = 0; t < 9; t++) {
            int i = t*256 + tid;
            int o = i / 72, k = i % 72;
            int tap = k >> 3, cl = k & 7;
            int gi = o*1152 + tap*128 + c0 + cl;
            sAh[o*AP + k] = g_wk1h[gi];
            sAl[o*AP + k] = g_wk1l[gi];
        }
        __syncthreads();

        #pragma unroll
        for (int tap = 0; tap < 9; tap++) {
            const int ty = tap / 3, tx = tap % 3;
            uint32_t ah[2][4], al[2][4];
            #pragma unroll
            for (int mt = 0; mt < 2; mt++) {
                const float* pah = sAh + (mt*16 + g)*AP + tap*8 + tig;
                const float* pal = sAl + (mt*16 + g)*AP + tap*8 + tig;
                ah[mt][0] = __float_as_uint(pah[0]);
                ah[mt][1] = __float_as_uint(pah[8*AP]);
                ah[mt][2] = __float_as_uint(pah[4]);
                ah[mt][3] = __float_as_uint(pah[8*AP + 4]);
                al[mt][0] = __float_as_uint(pal[0]);
                al[mt][1] = __float_as_uint(pal[8*AP]);
                al[mt][2] = __float_as_uint(pal[4]);
                al[mt][3] = __float_as_uint(pal[8*AP + 4]);
            }
            const float* pbh = sxh + tig*XSTR + (hh + ty)*ROWP + 3 + tx + wc0 + g;
            const float* pbl = sxl + tig*XSTR + (hh + ty)*ROWP + 3 + tx + wc0 + g;
            #pragma unroll
            for (int nt = 0; nt < 4; nt++) {
                uint32_t bh0 = __float_as_uint(pbh[nt*8]);
                uint32_t bh1 = __float_as_uint(pbh[nt*8 + 4*XSTR]);
                uint32_t bl0 = __float_as_uint(pbl[nt*8]);
                uint32_t bl1 = __float_as_uint(pbl[nt*8 + 4*XSTR]);
                #pragma unroll
                for (int mt = 0; mt < 2; mt++) {
                    mma_tf32(acc[mt][nt], ah[mt][0], ah[mt][1], ah[mt][2], ah[mt][3], bh0, bh1);
                    mma_tf32(acc[mt][nt], ah[mt][0], ah[mt][1], ah[mt][2], ah[mt][3], bl0, bl1);
                    mma_tf32(acc[mt][nt], al[mt][0], al[mt][1], al[mt][2], al[mt][3], bh0, bh1);
                }
            }
        }
    }

    float* omb = g_om + (size_t)b*32*HWn + (h0 + hh)*Wn + wc0;
    #pragma unroll
    for (int mt = 0; mt < 2; mt++) {
        int o0 = mt*16 + g;
        #pragma unroll
        for (int nt = 0; nt < 4; nt++) {
            int col = nt*8 + 2*tig;
            *(float2*)(omb + (size_t)o0*HWn + col) =
                make_float2(acc[mt][nt][0], acc[mt][nt][1]);
            *(float2*)(omb + (size_t)(o0+8)*HWn + col) =
                make_float2(acc[mt][nt][2], acc[mt][nt][3]);
        }
    }
}

// ---------------------------------------------------------------------------
// K2: bilinear gather * mask + depthwise 3x3, channel-vectorized.
// R9 changes vs R8: 4 warps/CTA (128 thr), 16 px per warp (2x warp count ->
// occupancy ~14 -> ~28 warps/SM), and w_dw moved regs -> smem transposed
// [k][c] (LDS.128 per tap, conflict-free) to cut regs ~88 -> ~50.
// ---------------------------------------------------------------------------
__global__ __launch_bounds__(128) void k2_sample(const float* __restrict__ w_dw,
                                                 const float* __restrict__ b_dw,
                                                 const float* __restrict__ b_off) {
    __shared__ float stap[4*16*72];     // [warp][px][tap][{idx4,wt4}]
    __shared__ float swdwT[9][128];     // [k][c]
    __shared__ float sbdw[128];

    int tid = threadIdx.x, wid = tid >> 5, lid = tid & 31;
    int b  = blockIdx.z;
    int w0 = blockIdx.x * 16;
    int h  = blockIdx.y * 4 + wid;      // each warp owns one row

    for (int i = tid; i < 9*128; i += 128) swdwT[i >> 7][i & 127] = w_dw[(i & 127)*9 + (i >> 7)];
    sbdw[tid] = b_dw[tid];
    __syncthreads();

    // ---- phase 1: lanes 0..15 compute tap tables for this warp's 16 px ----
    if (lid < 16) {
        int w = w0 + lid;
        const float* omb = g_om + (size_t)b*32*HWn + h*Wn + w;
        float* myt = stap + (wid*16 + lid)*72;
        #pragma unroll
        for (int k = 0; k < 9; k++) {
            float dyv = omb[(size_t)(2*k)*HWn]   + b_off[2*k];
            float dxv = omb[(size_t)(2*k+1)*HWn] + b_off[2*k+1];
            float mr  = omb[(size_t)(18+k)*HWn]  + b_off[18+k];
            float m = 1.f / (1.f + expf(-mr));
            float py = (float)(h + k/3 - 1) + dyv;
            float px = (float)(w + k%3 - 1) + dxv;
            float y0f = floorf(py), x0f = floorf(px);
            float wy = py - y0f, wx = px - x0f;
            int y0 = (int)y0f, x0 = (int)x0f;
            #pragma unroll
            for (int corner = 0; corner < 4; corner++) {
                int yy = y0 + (corner >> 1);
                int xx = x0 + (corner & 1);
                float bw = ((corner >> 1) ? wy : 1.f - wy) *
                           ((corner & 1)  ? wx : 1.f - wx);
                bool valid = (yy >= 0) && (yy < Hn) && (xx >= 0) && (xx < Wn);
                int yi = min(max(yy, 0), Hn-1);
                int xi = min(max(xx, 0), Wn-1);
                ((uint32_t*)myt)[k*8 + corner] = (uint32_t)((yi*Wn + xi) * 512);
                myt[k*8 + 4 + corner] = valid ? bw * m : 0.f;
            }
        }
    }
    __syncwarp();

    // ---- phase 2: sweep this warp's 16 pixels ----
    const char* xTb = (const char*)g_xT + (size_t)b*HWn*512 + lid*16;
    float* midb = g_mid + (size_t)b*HWn*128 + lid*4;
    const float* wt_base = stap + wid*16*72;
    float4 bd = *(const float4*)(sbdw + lid*4);

    for (int pi = 0; pi < 16; pi++) {
        const float* te = wt_base + pi*72;
        float a0 = bd.x, a1 = bd.y, a2 = bd.z, a3 = bd.w;
        #pragma unroll
        for (int k = 0; k < 9; k++) {
            uint4  I  = *(const uint4*)(te + k*8);        // broadcast LDS
            float4 Wt = *(const float4*)(te + k*8 + 4);
            float4 wk = *(const float4*)(&swdwT[k][lid*4]); // LDS.128, no conflict
            float4 x0 = *(const float4*)(xTb + I.x);
            float4 x1 = *(const float4*)(xTb + I.y);
            float4 x2 = *(const float4*)(xTb + I.z);
            float4 x3 = *(const float4*)(xTb + I.w);
            float v0 = Wt.x*x0.x + Wt.y*x1.x + Wt.z*x2.x + Wt.w*x3.x;
            float v1 = Wt.x*x0.y + Wt.y*x1.y + Wt.z*x2.y + Wt.w*x3.y;
            float v2 = Wt.x*x0.z + Wt.y*x1.z + Wt.z*x2.z + Wt.w*x3.z;
            float v3 = Wt.x*x0.w + Wt.y*x1.w + Wt.z*x2.w + Wt.w*x3.w;
            a0 = fmaf(wk.x, v0, a0);
            a1 = fmaf(wk.y, v1, a1);
            a2 = fmaf(wk.z, v2, a2);
            a3 = fmaf(wk.w, v3, a3);
        }
        int pg = h*Wn + w0 + pi;
        *(float4*)(midb + (size_t)pg*128) = make_float4(a0, a1, a2, a3);
    }
}

// ---------------------------------------------------------------------------
// K3: pointwise 1x1 as tf32 mma.sync GEMM; B staged from mid[p][c]. (unchanged)
// ---------------------------------------------------------------------------
#define PA 132
#define PC 132
#define K3_SMEM ((128*PA + 128*PC) * 4)

__global__ __launch_bounds__(256) void k3_mma(const float* __restrict__ w_pw,
                                              const float* __restrict__ b_pw,
                                              float* __restrict__ out) {
    extern __shared__ uint32_t smem[];
    uint32_t* sA = smem;             // 128 o x PA  (K-major along c)
    uint32_t* sB = smem + 128*PA;    // 128 px x PC (K-major along c)

    int tid = threadIdx.x;
    int wid = tid >> 5, lid = tid & 31;
    int g = lid >> 2, tig = lid & 3;
    int wm = wid >> 2, wn = wid & 3;

    int o0  = blockIdx.y * 128;
    int p0  = blockIdx.x * 128;
    int b   = p0 / HWn;
    int hw0 = p0 % HWn;

    #pragma unroll
    for (int it = 0; it < 16; it++) {
        int i = it*256 + tid;
        int m = i >> 5, q = i & 31;
        float4 v = *(const float4*)(w_pw + (size_t)(o0 + m)*Cn + q*4);
        uint4 u = { f2tf32(v.x), f2tf32(v.y), f2tf32(v.z), f2tf32(v.w) };
        *(uint4*)(sA + m*PA + q*4) = u;
    }
    const float* midb = g_mid + (size_t)p0*128;
    #pragma unroll
    for (int it = 0; it < 16; it++) {
        int i = it*256 + tid;
        int px = i >> 5, q = i & 31;
        float4 val = *(const float4*)(midb + (size_t)px*128 + q*4);
        uint4 u = { f2tf32(val.x), f2tf32(val.y), f2tf32(val.z), f2tf32(val.w) };
        *(uint4*)(sB + px*PC + q*4) = u;
    }
    __syncthreads();

    float acc[4][4][4];
    #pragma unroll
    for (int mi = 0; mi < 4; mi++)
        #pragma unroll
        for (int ni = 0; ni < 4; ni++)
            #pragma unroll
            for (int j = 0; j < 4; j++) acc[mi][ni][j] = 0.f;

    const uint32_t* sAr = sA + (wm*64 + g)*PA;
    const uint32_t* sBr = sB + (wn*32 + g)*PC;

    #pragma unroll
    for (int ks = 0; ks < 16; ks++) {
        int c0 = ks*8;
        uint32_t a[4][4], bf[4][2];
        #pragma unroll
        for (int mi = 0; mi < 4; mi++) {
            const uint32_t* p = sAr + mi*16*PA + c0 + tig;
            a[mi][0] = p[0];
            a[mi][1] = p[8*PA];
            a[mi][2] = p[4];
            a[mi][3] = p[8*PA + 4];
        }
        #pragma unroll
        for (int ni = 0; ni < 4; ni++) {
            const uint32_t* p = sBr + ni*8*PC + c0 + tig;
            bf[ni][0] = p[0];
            bf[ni][1] = p[4];
        }
        #pragma unroll
        for (int mi = 0; mi < 4; mi++)
            #pragma unroll
            for (int ni = 0; ni < 4; ni++)
                mma_tf32(acc[mi][ni], a[mi][0], a[mi][1], a[mi][2], a[mi][3],
                         bf[ni][0], bf[ni][1]);
    }

    float* outb = out + (size_t)b*On*HWn + hw0 + wn*32;
    #pragma unroll
    for (int mi = 0; mi < 4; mi++) {
        int row = o0 + wm*64 + mi*16 + g;
        float bias0 = b_pw[row];
        float bias1 = b_pw[row + 8];
        float* r0 = outb + (size_t)row*HWn;
        float* r1 = outb + (size_t)(row + 8)*HWn;
        #pragma unroll
        for (int ni = 0; ni < 4; ni++) {
            int col = ni*8 + 2*tig;
            *(float2*)(r0 + col) = make_float2(acc[mi][ni][0] + bias0,
                                               acc[mi][ni][1] + bias0);
            *(float2*)(r1 + col) = make_float2(acc[mi][ni][2] + bias1,
                                               acc[mi][ni][3] + bias1);
        }
    }
}

// ---------------------------------------------------------------------------
extern "C" void kernel_launch(void* const* d_in, const int* in_sizes, int n_in,
                              void* d_out, int out_size) {
    const float* x     = (const float*)d_in[0];
    const float* w_off = (const float*)d_in[1];
    const float* b_off = (const float*)d_in[2];
    const float* w_dw  = (const float*)d_in[3];
    const float* b_dw  = (const float*)d_in[4];
    const float* w_pw  = (const float*)d_in[5];
    const float* b_pw  = (const float*)d_in[6];
    float* out = (float*)d_out;

    cudaFuncSetAttribute(k1_mma, cudaFuncAttributeMaxDynamicSharedMemorySize, K1_SMEM);
    cudaFuncSetAttribute(k3_mma, cudaFuncAttributeMaxDynamicSharedMemorySize, K3_SMEM);

    k0_wk1   <<<(32*1152 + 255)/256, 256>>>(w_off);
    kT       <<<dim3(HWn/32, Cn/32, Bn), 256>>>(x);
    k1_mma   <<<dim3(Hn/2, Bn), 256, K1_SMEM>>>(x);
    k2_sample<<<dim3(Wn/16, Hn/4, Bn), 128>>>(w_dw, b_dw, b_off);
    k3_mma   <<<dim3(Bn*HWn/128, On/128), 256, K3_SMEM>>>(w_pw, b_pw, out);
}

// round 11
// speedup vs baseline: 1.0953x; 1.0953x over previous
#include <cuda_runtime.h>
#include <cuda_fp16.h>
#include <cstdint>

#define Bn 4
#define Cn 128
#define Hn 128
#define Wn 128
#define On 256
#define HWn (Hn*Wn)

// Scratch (allocation-free rule: __device__ globals)
__device__ float  g_mid[Bn*HWn*Cn];     // depthwise output, [p][c] layout
__device__ __half g_xTh[Bn*HWn*Cn];     // x transposed to [b][h][w][c], fp16
__device__ float  g_om[Bn*32*HWn];      // raw offset-conv output, 32 ch (27 used)
__device__ float  g_wk1h[32*9*128];     // offset-conv weights tf32-hi [o][tap][c]
__device__ float  g_wk1l[32*9*128];     // offset-conv weights tf32-lo

__device__ __forceinline__ uint32_t f2tf32(float f) {
    uint32_t u;
    asm("cvt.rna.tf32.f32 %0, %1;" : "=r"(u) : "f"(f));
    return u;
}

__device__ __forceinline__ void mma_tf32(float* d,
                                         uint32_t a0, uint32_t a1, uint32_t a2, uint32_t a3,
                                         uint32_t b0, uint32_t b1) {
    asm volatile(
        "mma.sync.aligned.m16n8k8.row.col.f32.tf32.tf32.f32 "
        "{%0,%1,%2,%3}, {%4,%5,%6,%7}, {%8,%9}, {%0,%1,%2,%3};"
        : "+f"(d[0]), "+f"(d[1]), "+f"(d[2]), "+f"(d[3])
        : "r"(a0), "r"(a1), "r"(a2), "r"(a3), "r"(b0), "r"(b1));
}

// ---------------------------------------------------------------------------
// K0: build tf32 hi/lo split of offset-conv weights as [o pad32][tap][c].
// ---------------------------------------------------------------------------
__global__ void k0_wk1(const float* __restrict__ w_off) {
    int idx = blockIdx.x * 256 + threadIdx.x;
    if (idx >= 32*1152) return;
    int o = idx / 1152, r = idx % 1152;      // r = tap*128 + c
    int tap = r >> 7, c = r & 127;
    float v = (o < 27) ? w_off[(o*Cn + c)*9 + tap] : 0.f;
    uint32_t hi = f2tf32(v);
    g_wk1h[idx] = __uint_as_float(hi);
    g_wk1l[idx] = __uint_as_float(f2tf32(v - __uint_as_float(hi)));
}

// ---------------------------------------------------------------------------
// KT: transpose x [b][c][h][w] -> xTh [b][hw][c] fp16 (channels contiguous).
// ---------------------------------------------------------------------------
__global__ __launch_bounds__(256) void kT(const float* __restrict__ x) {
    __shared__ float t[32][33];
    int b = blockIdx.z;
    int p0 = blockIdx.x * 32, c0 = blockIdx.y * 32;
    int tx = threadIdx.x & 31, ty = threadIdx.x >> 5;  // 32 x 8
    #pragma unroll
    for (int j = 0; j < 4; j++)
        t[ty + j*8][tx] = x[((size_t)b*Cn + c0 + ty + j*8)*HWn + p0 + tx];
    __syncthreads();
    #pragma unroll
    for (int j = 0; j < 4; j++)
        g_xTh[((size_t)b*HWn + p0 + ty + j*8)*128 + c0 + tx] =
            __float2half(t[tx][ty + j*8]);
}

// ---------------------------------------------------------------------------
// K1: offset/mask conv as tf32 mma.sync GEMM with 3-MMA precision split.
// (unchanged)
// ---------------------------------------------------------------------------
#define ROWP 136
#define XSTR 552
#define AP   76
#define K1_SMEM ((16*XSTR + 64*AP) * 4)

__global__ __launch_bounds__(256) void k1_mma(const float* __restrict__ x) {
    extern __shared__ float sm[];
    float* sxh = sm;
    float* sxl = sm + 8*XSTR;
    float* sAh = sm + 16*XSTR;
    float* sAl = sAh + 32*AP;

    int tid = threadIdx.x, wid = tid >> 5, lid = tid & 31;
    int g = lid >> 2, tig = lid & 3;
    int h0 = blockIdx.x * 2, b = blockIdx.y;

    for (int i = tid; i < 16*XSTR; i += 256) sm[i] = 0.f;

    float acc[2][4][4];
    #pragma unroll
    for (int mt = 0; mt < 2; mt++)
        #pragma unroll
        for (int nt = 0; nt < 4; nt++)
            #pragma unroll
            for (int j = 0; j < 4; j++) acc[mt][nt][j] = 0.f;

    int hh  = wid >> 2;
    int wc0 = (wid & 3) * 32;

    int s_cl = tid >> 5;
    int s_r  = (tid >> 3) & 3;
    int s_q  = tid & 7;

    for (int c0 = 0; c0 < Cn; c0 += 8) {
        __syncthreads();
        {
            int row = h0 - 1 + s_r;
            bool ok = (row >= 0) && (row < Hn);
            const float* xp = x + ((size_t)b*Cn + (c0 + s_cl))*HWn + row*Wn;
            float* dh = sxh + s_cl*XSTR + s_r*ROWP + 4;
            float* dl = sxl + s_cl*XSTR + s_r*ROWP + 4;
            #pragma unroll
            for (int j = 0; j < 4; j++) {
                int col = (s_q + 8*j) * 4;
                float4 v = ok ? *(const float4*)(xp + col) : make_float4(0.f,0.f,0.f,0.f);
                uint4 vh = { f2tf32(v.x), f2tf32(v.y), f2tf32(v.z), f2tf32(v.w) };
                uint4 vl = { f2tf32(v.x - __uint_as_float(vh.x)),
                             f2tf32(v.y - __uint_as_float(vh.y)),
                             f2tf32(v.z - __uint_as_float(vh.z)),
                             f2tf32(v.w - __uint_as_float(vh.w)) };
                *(uint4*)(dh + col) = vh;
                *(uint4*)(dl + col) = vl;
            }
        }
        #pragma unroll
        for (int t = 0; t < 9; t++) {
            int i = t*256 + tid;
            int o = i / 72, k = i % 72;
            int tap = k >> 3, cl = k & 7;
            int gi = o*1152 + tap*128 + c0 + cl;
            sAh[o*AP + k] = g_wk1h[gi];
            sAl[o*AP + k] = g_wk1l[gi];
        }
        __syncthreads();

        #pragma unroll
        for (int tap = 0; tap < 9; tap++) {
            const int ty = tap / 3, tx = tap % 3;
            uint32_t ah[2][4], al[2][4];
            #pragma unroll
            for (int mt = 0; mt < 2; mt++) {
                const float* pah = sAh + (mt*16 + g)*AP + tap*8 + tig;
                const float* pal = sAl + (mt*16 + g)*AP + tap*8 + tig;
                ah[mt][0] = __float_as_uint(pah[0]);
                ah[mt][1] = __float_as_uint(pah[8*AP]);
                ah[mt][2] = __float_as_uint(pah[4]);
                ah[mt][3] = __float_as_uint(pah[8*AP + 4]);
                al[mt][0] = __float_as_uint(pal[0]);
                al[mt][1] = __float_as_uint(pal[8*AP]);
                al[mt][2] = __float_as_uint(pal[4]);
                al[mt][3] = __float_as_uint(pal[8*AP + 4]);
            }
            const float* pbh = sxh + tig*XSTR + (hh + ty)*ROWP + 3 + tx + wc0 + g;
            const float* pbl = sxl + tig*XSTR + (hh + ty)*ROWP + 3 + tx + wc0 + g;
            #pragma unroll
            for (int nt = 0; nt < 4; nt++) {
                uint32_t bh0 = __float_as_uint(pbh[nt*8]);
                uint32_t bh1 = __float_as_uint(pbh[nt*8 + 4*XSTR]);
                uint32_t bl0 = __float_as_uint(pbl[nt*8]);
                uint32_t bl1 = __float_as_uint(pbl[nt*8 + 4*XSTR]);
                #pragma unroll
                for (int mt = 0; mt < 2; mt++) {
                    mma_tf32(acc[mt][nt], ah[mt][0], ah[mt][1], ah[mt][2], ah[mt][3], bh0, bh1);
                    mma_tf32(acc[mt][nt], ah[mt][0], ah[mt][1], ah[mt][2], ah[mt][3], bl0, bl1);
                    mma_tf32(acc[mt][nt], al[mt][0], al[mt][1], al[mt][2], al[mt][3], bh0, bh1);
                }
            }
        }
    }

    float* omb = g_om + (size_t)b*32*HWn + (h0 + hh)*Wn + wc0;
    #pragma unroll
    for (int mt = 0; mt < 2; mt++) {
        int o0 = mt*16 + g;
        #pragma unroll
        for (int nt = 0; nt < 4; nt++) {
            int col = nt*8 + 2*tig;
            *(float2*)(omb + (size_t)o0*HWn + col) =
                make_float2(acc[mt][nt][0], acc[mt][nt][1]);
            *(float2*)(omb + (size_t)(o0+8)*HWn + col) =
                make_float2(acc[mt][nt][2], acc[mt][nt][3]);
        }
    }
}

// ---------------------------------------------------------------------------
// K2: bilinear gather * mask + depthwise 3x3, channel-vectorized, fp16 x.
// Each corner gather = one coalesced LDG.64 (32 lanes x 8B = 256B channel
// vector): 72 L1 wavefronts/px instead of 144. Blend in fp32 after cvt.
// ---------------------------------------------------------------------------
__global__ __launch_bounds__(128) void k2_sample(const float* __restrict__ w_dw,
                                                 const float* __restrict__ b_dw,
                                                 const float* __restrict__ b_off) {
    __shared__ float stap[4*16*72];     // [warp][px][tap][{idx4,wt4}]
    __shared__ float swdwT[9][128];     // [k][c]
    __shared__ float sbdw[128];

    int tid = threadIdx.x, wid = tid >> 5, lid = tid & 31;
    int b  = blockIdx.z;
    int w0 = blockIdx.x * 16;
    int h  = blockIdx.y * 4 + wid;      // each warp owns one row

    for (int i = tid; i < 9*128; i += 128) swdwT[i >> 7][i & 127] = w_dw[(i & 127)*9 + (i >> 7)];
    sbdw[tid] = b_dw[tid];
    __syncthreads();

    // ---- phase 1: lanes 0..15 compute tap tables for this warp's 16 px ----
    if (lid < 16) {
        int w = w0 + lid;
        const float* omb = g_om + (size_t)b*32*HWn + h*Wn + w;
        float* myt = stap + (wid*16 + lid)*72;
        #pragma unroll
        for (int k = 0; k < 9; k++) {
            float dyv = omb[(size_t)(2*k)*HWn]   + b_off[2*k];
            float dxv = omb[(size_t)(2*k+1)*HWn] + b_off[2*k+1];
            float mr  = omb[(size_t)(18+k)*HWn]  + b_off[18+k];
            float m = 1.f / (1.f + expf(-mr));
            float py = (float)(h + k/3 - 1) + dyv;
            float px = (float)(w + k%3 - 1) + dxv;
            float y0f = floorf(py), x0f = floorf(px);
            float wy = py - y0f, wx = px - x0f;
            int y0 = (int)y0f, x0 = (int)x0f;
            #pragma unroll
            for (int corner = 0; corner < 4; corner++) {
                int yy = y0 + (corner >> 1);
                int xx = x0 + (corner & 1);
                float bw = ((corner >> 1) ? wy : 1.f - wy) *
                           ((corner & 1)  ? wx : 1.f - wx);
                bool valid = (yy >= 0) && (yy < Hn) && (xx >= 0) && (xx < Wn);
                int yi = min(max(yy, 0), Hn-1);
                int xi = min(max(xx, 0), Wn-1);
                ((uint32_t*)myt)[k*8 + corner] = (uint32_t)((yi*Wn + xi) * 256);
                myt[k*8 + 4 + corner] = valid ? bw * m : 0.f;
            }
        }
    }
    __syncwarp();

    // ---- phase 2: sweep this warp's 16 pixels ----
    const char* xTb = (const char*)g_xTh + (size_t)b*HWn*256 + lid*8;
    float* midb = g_mid + (size_t)b*HWn*128 + lid*4;
    const float* wt_base = stap + wid*16*72;
    float4 bd = *(const float4*)(sbdw + lid*4);

    for (int pi = 0; pi < 16; pi++) {
        const float* te = wt_base + pi*72;
        float a0 = bd.x, a1 = bd.y, a2 = bd.z, a3 = bd.w;
        #pragma unroll
        for (int k = 0; k < 9; k++) {
            uint4  I  = *(const uint4*)(te + k*8);          // broadcast LDS
            float4 Wt = *(const float4*)(te + k*8 + 4);
            float4 wk = *(const float4*)(&swdwT[k][lid*4]); // LDS.128, no conflict
            uint2 r0 = *(const uint2*)(xTb + I.x);          // LDG.64: 4 fp16 ch
            uint2 r1 = *(const uint2*)(xTb + I.y);
            uint2 r2 = *(const uint2*)(xTb + I.z);
            uint2 r3 = *(const uint2*)(xTb + I.w);
            float2 x0a = __half22float2(*(const __half2*)&r0.x);
            float2 x0b = __half22float2(*(const __half2*)&r0.y);
            float2 x1a = __half22float2(*(const __half2*)&r1.x);
            float2 x1b = __half22float2(*(const __half2*)&r1.y);
            float2 x2a = __half22float2(*(const __half2*)&r2.x);
            float2 x2b = __half22float2(*(const __half2*)&r2.y);
            float2 x3a = __half22float2(*(const __half2*)&r3.x);
            float2 x3b = __half22float2(*(const __half2*)&r3.y);
            float v0 = Wt.x*x0a.x + Wt.y*x1a.x + Wt.z*x2a.x + Wt.w*x3a.x;
            float v1 = Wt.x*x0a.y + Wt.y*x1a.y + Wt.z*x2a.y + Wt.w*x3a.y;
            float v2 = Wt.x*x0b.x + Wt.y*x1b.x + Wt.z*x2b.x + Wt.w*x3b.x;
            float v3 = Wt.x*x0b.y + Wt.y*x1b.y + Wt.z*x2b.y + Wt.w*x3b.y;
            a0 = fmaf(wk.x, v0, a0);
            a1 = fmaf(wk.y, v1, a1);
            a2 = fmaf(wk.z, v2, a2);
            a3 = fmaf(wk.w, v3, a3);
        }
        int pg = h*Wn + w0 + pi;
        *(float4*)(midb + (size_t)pg*128) = make_float4(a0, a1, a2, a3);
    }
}

// ---------------------------------------------------------------------------
// K3: pointwise 1x1 as tf32 mma.sync GEMM; B staged from mid[p][c]. (unchanged)
// ---------------------------------------------------------------------------
#define PA 132
#define PC 132
#define K3_SMEM ((128*PA + 128*PC) * 4)

__global__ __launch_bounds__(256) void k3_mma(const float* __restrict__ w_pw,
                                              const float* __restrict__ b_pw,
                                              float* __restrict__ out) {
    extern __shared__ uint32_t smem[];
    uint32_t* sA = smem;             // 128 o x PA  (K-major along c)
    uint32_t* sB = smem + 128*PA;    // 128 px x PC (K-major along c)

    int tid = threadIdx.x;
    int wid = tid >> 5, lid = tid & 31;
    int g = lid >> 2, tig = lid & 3;
    int wm = wid >> 2, wn = wid & 3;

    int o0  = blockIdx.y * 128;
    int p0  = blockIdx.x * 128;
    int b   = p0 / HWn;
    int hw0 = p0 % HWn;

    #pragma unroll
    for (int it = 0; it < 16; it++) {
        int i = it*256 + tid;
        int m = i >> 5, q = i & 31;
        float4 v = *(const float4*)(w_pw + (size_t)(o0 + m)*Cn + q*4);
        uint4 u = { f2tf32(v.x), f2tf32(v.y), f2tf32(v.z), f2tf32(v.w) };
        *(uint4*)(sA + m*PA + q*4) = u;
    }
    const float* midb = g_mid + (size_t)p0*128;
    #pragma unroll
    for (int it = 0; it < 16; it++) {
        int i = it*256 + tid;
        int px = i >> 5, q = i & 31;
        float4 val = *(const float4*)(midb + (size_t)px*128 + q*4);
        uint4 u = { f2tf32(val.x), f2tf32(val.y), f2tf32(val.z), f2tf32(val.w) };
        *(uint4*)(sB + px*PC + q*4) = u;
    }
    __syncthreads();

    float acc[4][4][4];
    #pragma unroll
    for (int mi = 0; mi < 4; mi++)
        #pragma unroll
        for (int ni = 0; ni < 4; ni++)
            #pragma unroll
            for (int j = 0; j < 4; j++) acc[mi][ni][j] = 0.f;

    const uint32_t* sAr = sA + (wm*64 + g)*PA;
    const uint32_t* sBr = sB + (wn*32 + g)*PC;

    #pragma unroll
    for (int ks = 0; ks < 16; ks++) {
        int c0 = ks*8;
        uint32_t a[4][4], bf[4][2];
        #pragma unroll
        for (int mi = 0; mi < 4; mi++) {
            const uint32_t* p = sAr + mi*16*PA + c0 + tig;
            a[mi][0] = p[0];
            a[mi][1] = p[8*PA];
            a[mi][2] = p[4];
            a[mi][3] = p[8*PA + 4];
        }
        #pragma unroll
        for (int ni = 0; ni < 4; ni++) {
            const uint32_t* p = sBr + ni*8*PC + c0 + tig;
            bf[ni][0] = p[0];
            bf[ni][1] = p[4];
        }
        #pragma unroll
        for (int mi = 0; mi < 4; mi++)
            #pragma unroll
            for (int ni = 0; ni < 4; ni++)
                mma_tf32(acc[mi][ni], a[mi][0], a[mi][1], a[mi][2], a[mi][3],
                         bf[ni][0], bf[ni][1]);
    }

    float* outb = out + (size_t)b*On*HWn + hw0 + wn*32;
    #pragma unroll
    for (int mi = 0; mi < 4; mi++) {
        int row = o0 + wm*64 + mi*16 + g;
        float bias0 = b_pw[row];
        float bias1 = b_pw[row + 8];
        float* r0 = outb + (size_t)row*HWn;
        float* r1 = outb + (size_t)(row + 8)*HWn;
        #pragma unroll
        for (int ni = 0; ni < 4; ni++) {
            int col = ni*8 + 2*tig;
            *(float2*)(r0 + col) = make_float2(acc[mi][ni][0] + bias0,
                                               acc[mi][ni][1] + bias0);
            *(float2*)(r1 + col) = make_float2(acc[mi][ni][2] + bias1,
                                               acc[mi][ni][3] + bias1);
        }
    }
}

// ---------------------------------------------------------------------------
extern "C" void kernel_launch(void* const* d_in, const int* in_sizes, int n_in,
                              void* d_out, int out_size) {
    const float* x     = (const float*)d_in[0];
    const float* w_off = (const float*)d_in[1];
    const float* b_off = (const float*)d_in[2];
    const float* w_dw  = (const float*)d_in[3];
    const float* b_dw  = (const float*)d_in[4];
    const float* w_pw  = (const float*)d_in[5];
    const float* b_pw  = (const float*)d_in[6];
    float* out = (float*)d_out;

    cudaFuncSetAttribute(k1_mma, cudaFuncAttributeMaxDynamicSharedMemorySize, K1_SMEM);
    cudaFuncSetAttribute(k3_mma, cudaFuncAttributeMaxDynamicSharedMemorySize, K3_SMEM);

    k0_wk1   <<<(32*1152 + 255)/256, 256>>>(w_off);
    kT       <<<dim3(HWn/32, Cn/32, Bn), 256>>>(x);
    k1_mma   <<<dim3(Hn/2, Bn), 256, K1_SMEM>>>(x);
    k2_sample<<<dim3(Wn/16, Hn/4, Bn), 128>>>(w_dw, b_dw, b_off);
    k3_mma   <<<dim3(Bn*HWn/128, On/128), 256, K3_SMEM>>>(w_pw, b_pw, out);
}

// round 12
// speedup vs baseline: 1.1290x; 1.0308x over previous
#include <cuda_runtime.h>
#include <cuda_fp16.h>
#include <cstdint>

#define Bn 4
#define Cn 128
#define Hn 128
#define Wn 128
#define On 256
#define HWn (Hn*Wn)

// Scratch (allocation-free rule: __device__ globals)
__device__ float  g_mid[Bn*HWn*Cn];     // depthwise output, [p][c] layout
__device__ __half g_xTh[Bn*HWn*Cn];     // x transposed to [b][h][w][c], fp16
__device__ float  g_om[Bn*32*HWn];      // raw offset-conv output, 32 ch (27 used)
__device__ float  g_wk1h[32*9*128];     // offset-conv weights tf32-hi [o][tap][c]
__device__ float  g_wk1l[32*9*128];     // offset-conv weights tf32-lo

__device__ __forceinline__ uint32_t f2tf32(float f) {
    uint32_t u;
    asm("cvt.rna.tf32.f32 %0, %1;" : "=r"(u) : "f"(f));
    return u;
}

__device__ __forceinline__ void mma_tf32(float* d,
                                         uint32_t a0, uint32_t a1, uint32_t a2, uint32_t a3,
                                         uint32_t b0, uint32_t b1) {
    asm volatile(
        "mma.sync.aligned.m16n8k8.row.col.f32.tf32.tf32.f32 "
        "{%0,%1,%2,%3}, {%4,%5,%6,%7}, {%8,%9}, {%0,%1,%2,%3};"
        : "+f"(d[0]), "+f"(d[1]), "+f"(d[2]), "+f"(d[3])
        : "r"(a0), "r"(a1), "r"(a2), "r"(a3), "r"(b0), "r"(b1));
}

// ---------------------------------------------------------------------------
// K0: build tf32 hi/lo split of offset-conv weights as [o pad32][tap][c].
// ---------------------------------------------------------------------------
__global__ void k0_wk1(const float* __restrict__ w_off) {
    int idx = blockIdx.x * 256 + threadIdx.x;
    if (idx >= 32*1152) return;
    int o = idx / 1152, r = idx % 1152;      // r = tap*128 + c
    int tap = r >> 7, c = r & 127;
    float v = (o < 27) ? w_off[(o*Cn + c)*9 + tap] : 0.f;
    uint32_t hi = f2tf32(v);
    g_wk1h[idx] = __uint_as_float(hi);
    g_wk1l[idx] = __uint_as_float(f2tf32(v - __uint_as_float(hi)));
}

// ---------------------------------------------------------------------------
// KT: transpose x [b][c][h][w] -> xTh [b][hw][c] fp16 (channels contiguous).
// ---------------------------------------------------------------------------
__global__ __launch_bounds__(256) void kT(const float* __restrict__ x) {
    __shared__ float t[32][33];
    int b = blockIdx.z;
    int p0 = blockIdx.x * 32, c0 = blockIdx.y * 32;
    int tx = threadIdx.x & 31, ty = threadIdx.x >> 5;  // 32 x 8
    #pragma unroll
    for (int j = 0; j < 4; j++)
        t[ty + j*8][tx] = x[((size_t)b*Cn + c0 + ty + j*8)*HWn + p0 + tx];
    __syncthreads();
    #pragma unroll
    for (int j = 0; j < 4; j++)
        g_xTh[((size_t)b*HWn + p0 + ty + j*8)*128 + c0 + tx] =
            __float2half(t[tx][ty + j*8]);
}

// ---------------------------------------------------------------------------
// K1: offset/mask conv as tf32 mma.sync GEMM with 3-MMA precision split.
// (unchanged)
// ---------------------------------------------------------------------------
#define ROWP 136
#define XSTR 552
#define AP   76
#define K1_SMEM ((16*XSTR + 64*AP) * 4)

__global__ __launch_bounds__(256) void k1_mma(const float* __restrict__ x) {
    extern __shared__ float sm[];
    float* sxh = sm;
    float* sxl = sm + 8*XSTR;
    float* sAh = sm + 16*XSTR;
    float* sAl = sAh + 32*AP;

    int tid = threadIdx.x, wid = tid >> 5, lid = tid & 31;
    int g = lid >> 2, tig = lid & 3;
    int h0 = blockIdx.x * 2, b = blockIdx.y;

    for (int i = tid; i < 16*XSTR; i += 256) sm[i] = 0.f;

    float acc[2][4][4];
    #pragma unroll
    for (int mt = 0; mt < 2; mt++)
        #pragma unroll
        for (int nt = 0; nt < 4; nt++)
            #pragma unroll
            for (int j = 0; j < 4; j++) acc[mt][nt][j] = 0.f;

    int hh  = wid >> 2;
    int wc0 = (wid & 3) * 32;

    int s_cl = tid >> 5;
    int s_r  = (tid >> 3) & 3;
    int s_q  = tid & 7;

    for (int c0 = 0; c0 < Cn; c0 += 8) {
        __syncthreads();
        {
            int row = h0 - 1 + s_r;
            bool ok = (row >= 0) && (row < Hn);
            const float* xp = x + ((size_t)b*Cn + (c0 + s_cl))*HWn + row*Wn;
            float* dh = sxh + s_cl*XSTR + s_r*ROWP + 4;
            float* dl = sxl + s_cl*XSTR + s_r*ROWP + 4;
            #pragma unroll
            for (int j = 0; j < 4; j++) {
                int col = (s_q + 8*j) * 4;
                float4 v = ok ? *(const float4*)(xp + col) : make_float4(0.f,0.f,0.f,0.f);
                uint4 vh = { f2tf32(v.x), f2tf32(v.y), f2tf32(v.z), f2tf32(v.w) };
                uint4 vl = { f2tf32(v.x - __uint_as_float(vh.x)),
                             f2tf32(v.y - __uint_as_float(vh.y)),
                             f2tf32(v.z - __uint_as_float(vh.z)),
                             f2tf32(v.w - __uint_as_float(vh.w)) };
                *(uint4*)(dh + col) = vh;
                *(uint4*)(dl + col) = vl;
            }
        }
        #pragma unroll
        for (int t = 0; t < 9; t++) {
            int i = t*256 + tid;
            int o = i / 72, k = i % 72;
            int tap = k >> 3, cl = k & 7;
            int gi = o*1152 + tap*128 + c0 + cl;
            sAh[o*AP + k] = g_wk1h[gi];
            sAl[o*AP + k] = g_wk1l[gi];
        }
        __syncthreads();

        #pragma unroll
        for (int tap = 0; tap < 9; tap++) {
            const int ty = tap / 3, tx = tap % 3;
            uint32_t ah[2][4], al[2][4];
            #pragma unroll
            for (int mt = 0; mt < 2; mt++) {
                const float* pah = sAh + (mt*16 + g)*AP + tap*8 + tig;
                const float* pal = sAl + (mt*16 + g)*AP + tap*8 + tig;
                ah[mt][0] = __float_as_uint(pah[0]);
                ah[mt][1] = __float_as_uint(pah[8*AP]);
                ah[mt][2] = __float_as_uint(pah[4]);
                ah[mt][3] = __float_as_uint(pah[8*AP + 4]);
                al[mt][0] = __float_as_uint(pal[0]);
                al[mt][1] = __float_as_uint(pal[8*AP]);
                al[mt][2] = __float_as_uint(pal[4]);
                al[mt][3] = __float_as_uint(pal[8*AP + 4]);
            }
            const float* pbh = sxh + tig*XSTR + (hh + ty)*ROWP + 3 + tx + wc0 + g;
            const float* pbl = sxl + tig*XSTR + (hh + ty)*ROWP + 3 + tx + wc0 + g;
            #pragma unroll
            for (int nt = 0; nt < 4; nt++) {
                uint32_t bh0 = __float_as_uint(pbh[nt*8]);
                uint32_t bh1 = __float_as_uint(pbh[nt*8 + 4*XSTR]);
                uint32_t bl0 = __float_as_uint(pbl[nt*8]);
                uint32_t bl1 = __float_as_uint(pbl[nt*8 + 4*XSTR]);
                #pragma unroll
                for (int mt = 0; mt < 2; mt++) {
                    mma_tf32(acc[mt][nt], ah[mt][0], ah[mt][1], ah[mt][2], ah[mt][3], bh0, bh1);
                    mma_tf32(acc[mt][nt], ah[mt][0], ah[mt][1], ah[mt][2], ah[mt][3], bl0, bl1);
                    mma_tf32(acc[mt][nt], al[mt][0], al[mt][1], al[mt][2], al[mt][3], bh0, bh1);
                }
            }
        }
    }

    float* omb = g_om + (size_t)b*32*HWn + (h0 + hh)*Wn + wc0;
    #pragma unroll
    for (int mt = 0; mt < 2; mt++) {
        int o0 = mt*16 + g;
        #pragma unroll
        for (int nt = 0; nt < 4; nt++) {
            int col = nt*8 + 2*tig;
            *(float2*)(omb + (size_t)o0*HWn + col) =
                make_float2(acc[mt][nt][0], acc[mt][nt][1]);
            *(float2*)(omb + (size_t)(o0+8)*HWn + col) =
                make_float2(acc[mt][nt][2], acc[mt][nt][3]);
        }
    }
}

// ---------------------------------------------------------------------------
// K2: bilinear gather * mask + depthwise 3x3, channel-vectorized, fp16 x.
// R11: process pixels in PAIRS inside the tap loop -> 8 independent LDG.64
// per dependency chain (2x MLP), w_dw LDS amortized over the pair.
// ---------------------------------------------------------------------------
__global__ __launch_bounds__(128) void k2_sample(const float* __restrict__ w_dw,
                                                 const float* __restrict__ b_dw,
                                                 const float* __restrict__ b_off) {
    __shared__ float stap[4*16*72];     // [warp][px][tap][{idx4,wt4}]
    __shared__ float swdwT[9][128];     // [k][c]
    __shared__ float sbdw[128];

    int tid = threadIdx.x, wid = tid >> 5, lid = tid & 31;
    int b  = blockIdx.z;
    int w0 = blockIdx.x * 16;
    int h  = blockIdx.y * 4 + wid;      // each warp owns one row

    for (int i = tid; i < 9*128; i += 128) swdwT[i >> 7][i & 127] = w_dw[(i & 127)*9 + (i >> 7)];
    sbdw[tid] = b_dw[tid];
    __syncthreads();

    // ---- phase 1: lanes 0..15 compute tap tables for this warp's 16 px ----
    if (lid < 16) {
        int w = w0 + lid;
        const float* omb = g_om + (size_t)b*32*HWn + h*Wn + w;
        float* myt = stap + (wid*16 + lid)*72;
        #pragma unroll
        for (int k = 0; k < 9; k++) {
            float dyv = omb[(size_t)(2*k)*HWn]   + b_off[2*k];
            float dxv = omb[(size_t)(2*k+1)*HWn] + b_off[2*k+1];
            float mr  = omb[(size_t)(18+k)*HWn]  + b_off[18+k];
            float m = 1.f / (1.f + expf(-mr));
            float py = (float)(h + k/3 - 1) + dyv;
            float px = (float)(w + k%3 - 1) + dxv;
            float y0f = floorf(py), x0f = floorf(px);
            float wy = py - y0f, wx = px - x0f;
            int y0 = (int)y0f, x0 = (int)x0f;
            #pragma unroll
            for (int corner = 0; corner < 4; corner++) {
                int yy = y0 + (corner >> 1);
                int xx = x0 + (corner & 1);
                float bw = ((corner >> 1) ? wy : 1.f - wy) *
                           ((corner & 1)  ? wx : 1.f - wx);
                bool valid = (yy >= 0) && (yy < Hn) && (xx >= 0) && (xx < Wn);
                int yi = min(max(yy, 0), Hn-1);
                int xi = min(max(xx, 0), Wn-1);
                ((uint32_t*)myt)[k*8 + corner] = (uint32_t)((yi*Wn + xi) * 256);
                myt[k*8 + 4 + corner] = valid ? bw * m : 0.f;
            }
        }
    }
    __syncwarp();

    // ---- phase 2: sweep this warp's 16 pixels, two at a time ----
    const char* xTb = (const char*)g_xTh + (size_t)b*HWn*256 + lid*8;
    float* midb = g_mid + (size_t)b*HWn*128 + lid*4;
    const float* wt_base = stap + wid*16*72;
    float4 bd = *(const float4*)(sbdw + lid*4);

    #pragma unroll 2
    for (int pj = 0; pj < 8; pj++) {
        const float* te0 = wt_base + (2*pj)*72;
        const float* te1 = te0 + 72;
        float a0 = bd.x, a1 = bd.y, a2 = bd.z, a3 = bd.w;
        float c0 = bd.x, c1 = bd.y, c2 = bd.z, c3 = bd.w;
        #pragma unroll
        for (int k = 0; k < 9; k++) {
            uint4  I0  = *(const uint4*)(te0 + k*8);
            float4 Wt0 = *(const float4*)(te0 + k*8 + 4);
            uint4  I1  = *(const uint4*)(te1 + k*8);
            float4 Wt1 = *(const float4*)(te1 + k*8 + 4);
            float4 wk  = *(const float4*)(&swdwT[k][lid*4]);
            // 8 independent gathers
            uint2 p0 = *(const uint2*)(xTb + I0.x);
            uint2 p1 = *(const uint2*)(xTb + I0.y);
            uint2 p2 = *(const uint2*)(xTb + I0.z);
            uint2 p3 = *(const uint2*)(xTb + I0.w);
            uint2 q0 = *(const uint2*)(xTb + I1.x);
            uint2 q1 = *(const uint2*)(xTb + I1.y);
            uint2 q2 = *(const uint2*)(xTb + I1.z);
            uint2 q3 = *(const uint2*)(xTb + I1.w);
            // pixel 0 blend
            {
                float2 x0a = __half22float2(*(const __half2*)&p0.x);
                float2 x0b = __half22float2(*(const __half2*)&p0.y);
                float2 x1a = __half22float2(*(const __half2*)&p1.x);
                float2 x1b = __half22float2(*(const __half2*)&p1.y);
                float2 x2a = __half22float2(*(const __half2*)&p2.x);
                float2 x2b = __half22float2(*(const __half2*)&p2.y);
                float2 x3a = __half22float2(*(const __half2*)&p3.x);
                float2 x3b = __half22float2(*(const __half2*)&p3.y);
                float v0 = Wt0.x*x0a.x + Wt0.y*x1a.x + Wt0.z*x2a.x + Wt0.w*x3a.x;
                float v1 = Wt0.x*x0a.y + Wt0.y*x1a.y + Wt0.z*x2a.y + Wt0.w*x3a.y;
                float v2 = Wt0.x*x0b.x + Wt0.y*x1b.x + Wt0.z*x2b.x + Wt0.w*x3b.x;
                float v3 = Wt0.x*x0b.y + Wt0.y*x1b.y + Wt0.z*x2b.y + Wt0.w*x3b.y;
                a0 = fmaf(wk.x, v0, a0);
                a1 = fmaf(wk.y, v1, a1);
                a2 = fmaf(wk.z, v2, a2);
                a3 = fmaf(wk.w, v3, a3);
            }
            // pixel 1 blend
            {
                float2 x0a = __half22float2(*(const __half2*)&q0.x);
                float2 x0b = __half22float2(*(const __half2*)&q0.y);
                float2 x1a = __half22float2(*(const __half2*)&q1.x);
                float2 x1b = __half22float2(*(const __half2*)&q1.y);
                float2 x2a = __half22float2(*(const __half2*)&q2.x);
                float2 x2b = __half22float2(*(const __half2*)&q2.y);
                float2 x3a = __half22float2(*(const __half2*)&q3.x);
                float2 x3b = __half22float2(*(const __half2*)&q3.y);
                float v0 = Wt1.x*x0a.x + Wt1.y*x1a.x + Wt1.z*x2a.x + Wt1.w*x3a.x;
                float v1 = Wt1.x*x0a.y + Wt1.y*x1a.y + Wt1.z*x2a.y + Wt1.w*x3a.y;
                float v2 = Wt1.x*x0b.x + Wt1.y*x1b.x + Wt1.z*x2b.x + Wt1.w*x3b.x;
                float v3 = Wt1.x*x0b.y + Wt1.y*x1b.y + Wt1.z*x2b.y + Wt1.w*x3b.y;
                c0 = fmaf(wk.x, v0, c0);
                c1 = fmaf(wk.y, v1, c1);
                c2 = fmaf(wk.z, v2, c2);
                c3 = fmaf(wk.w, v3, c3);
            }
        }
        int pg = h*Wn + w0 + 2*pj;
        *(float4*)(midb + (size_t)pg*128)       = make_float4(a0, a1, a2, a3);
        *(float4*)(midb + (size_t)(pg+1)*128)   = make_float4(c0, c1, c2, c3);
    }
}

// ---------------------------------------------------------------------------
// K3: pointwise 1x1 as tf32 mma.sync GEMM — persistent CTAs.
// Grid (148, 2): CTA pins its A tile (o-block) in smem once, loops over px
// tiles t = bx, bx+148, ... with double-buffered B and ONE sync per tile.
// Prefetch of next tile's B interleaves with current tile's 16 k-steps.
// ---------------------------------------------------------------------------
#define PA 132
#define PC 132
#define NTILES (Bn*HWn/128)          // 512
#define K3_SMEM ((128*PA + 2*128*PC) * 4)

__global__ __launch_bounds__(256) void k3_mma(const float* __restrict__ w_pw,
                                              const float* __restrict__ b_pw,
                                              float* __restrict__ out) {
    extern __shared__ uint32_t smem[];
    uint32_t* sA = smem;                       // 128 o x PA
    uint32_t* sB0 = smem + 128*PA;             // 128 px x PC (buf 0)
    uint32_t* sB1 = sB0 + 128*PC;              // buf 1

    int tid = threadIdx.x;
    int wid = tid >> 5, lid = tid & 31;
    int g = lid >> 2, tig = lid & 3;
    int wm = wid >> 2, wn = wid & 3;

    int o0 = blockIdx.y * 128;

    // ---- stage A once ----
    #pragma unroll
    for (int it = 0; it < 16; it++) {
        int i = it*256 + tid;
        int m = i >> 5, q = i & 31;
        float4 v = *(const float4*)(w_pw + (size_t)(o0 + m)*Cn + q*4);
        uint4 u = { f2tf32(v.x), f2tf32(v.y), f2tf32(v.z), f2tf32(v.w) };
        *(uint4*)(sA + m*PA + q*4) = u;
    }

    // bias registers (two rows this thread stores per mi)
    float biasr[4][2];
    #pragma unroll
    for (int mi = 0; mi < 4; mi++) {
        int row = o0 + wm*64 + mi*16 + g;
        biasr[mi][0] = b_pw[row];
        biasr[mi][1] = b_pw[row + 8];
    }

    // staging map: i = j*256+tid -> px = i>>4, qh = i&15 (within a c-half)
    int s_px = tid >> 4;          // base px, +16 per j
    int s_qh = tid & 15;          // float4 index within half

    // ---- prologue: stage B(tile bx) into buf0 ----
    int t = blockIdx.x;
    {
        const float* midb = g_mid + (size_t)t*128*128;
        #pragma unroll
        for (int h = 0; h < 2; h++) {
            #pragma unroll
            for (int j = 0; j < 8; j++) {
                int px = s_px + j*16, q = s_qh + h*16;
                float4 v = *(const float4*)(midb + (size_t)px*128 + q*4);
                uint4 u = { f2tf32(v.x), f2tf32(v.y), f2tf32(v.z), f2tf32(v.w) };
                *(uint4*)(sB0 + px*PC + q*4) = u;
            }
        }
    }
    __syncthreads();

    int cur = 0;
    while (t < NTILES) {
        uint32_t* sB  = cur ? sB1 : sB0;
        uint32_t* sBn = cur ? sB0 : sB1;
        int tn = t + 148;
        bool pf = tn < NTILES;
        const float* midn = g_mid + (size_t)tn*128*128;

        float acc[4][4][4];
        #pragma unroll
        for (int mi = 0; mi < 4; mi++)
            #pragma unroll
            for (int ni = 0; ni < 4; ni++)
                #pragma unroll
                for (int j = 0; j < 4; j++) acc[mi][ni][j] = 0.f;

        const uint32_t* sAr = sA + (wm*64 + g)*PA;
        const uint32_t* sBr = sB + (wn*32 + g)*PC;

        // ---- prefetch half 0 of next tile ----
        float4 r0[8];
        if (pf) {
            #pragma unroll
            for (int j = 0; j < 8; j++)
                r0[j] = *(const float4*)(midn + (size_t)(s_px + j*16)*128 + s_qh*4);
        }

        // ---- MMA ks 0..7 ----
        #pragma unroll
        for (int ks = 0; ks < 8; ks++) {
            int c0 = ks*8;
            uint32_t a[4][4], bf[4][2];
            #pragma unroll
            for (int mi = 0; mi < 4; mi++) {
                const uint32_t* p = sAr + mi*16*PA + c0 + tig;
                a[mi][0] = p[0]; a[mi][1] = p[8*PA]; a[mi][2] = p[4]; a[mi][3] = p[8*PA + 4];
            }
            #pragma unroll
            for (int ni = 0; ni < 4; ni++) {
                const uint32_t* p = sBr + ni*8*PC + c0 + tig;
                bf[ni][0] = p[0]; bf[ni][1] = p[4];
            }
            #pragma unroll
            for (int mi = 0; mi < 4; mi++)
                #pragma unroll
                for (int ni = 0; ni < 4; ni++)
                    mma_tf32(acc[mi][ni], a[mi][0], a[mi][1], a[mi][2], a[mi][3],
                             bf[ni][0], bf[ni][1]);
        }

        // ---- store half 0, prefetch half 1 ----
        float4 r1[8];
        if (pf) {
            #pragma unroll
            for (int j = 0; j < 8; j++) {
                uint4 u = { f2tf32(r0[j].x), f2tf32(r0[j].y), f2tf32(r0[j].z), f2tf32(r0[j].w) };
                *(uint4*)(sBn + (s_px + j*16)*PC + s_qh*4) = u;
            }
            #pragma unroll
            for (int j = 0; j < 8; j++)
                r1[j] = *(const float4*)(midn + (size_t)(s_px + j*16)*128 + (s_qh + 16)*4);
        }

        // ---- MMA ks 8..15 ----
        #pragma unroll
        for (int ks = 8; ks < 16; ks++) {
            int c0 = ks*8;
            uint32_t a[4][4], bf[4][2];
            #pragma unroll
            for (int mi = 0; mi < 4; mi++) {
                const uint32_t* p = sAr + mi*16*PA + c0 + tig;
                a[mi][0] = p[0]; a[mi][1] = p[8*PA]; a[mi][2] = p[4]; a[mi][3] = p[8*PA + 4];
            }
            #pragma unroll
            for (int ni = 0; ni < 4; ni++) {
                const uint32_t* p = sBr + ni*8*PC + c0 + tig;
                bf[ni][0] = p[0]; bf[ni][1] = p[4];
            }
            #pragma unroll
            for (int mi = 0; mi < 4; mi++)
                #pragma unroll
                for (int ni = 0; ni < 4; ni++)
                    mma_tf32(acc[mi][ni], a[mi][0], a[mi][1], a[mi][2], a[mi][3],
                             bf[ni][0], bf[ni][1]);
        }

        // ---- store half 1 of next tile ----
        if (pf) {
            #pragma unroll
            for (int j = 0; j < 8; j++) {
                uint4 u = { f2tf32(r1[j].x), f2tf32(r1[j].y), f2tf32(r1[j].z), f2tf32(r1[j].w) };
                *(uint4*)(sBn + (s_px + j*16)*PC + (s_qh + 16)*4) = u;
            }
        }

        // ---- epilogue for tile t ----
        {
            int p0  = t * 128;
            int b   = p0 / HWn;
            int hw0 = p0 % HWn;
            float* outb = out + (size_t)b*On*HWn + hw0 + wn*32;
            #pragma unroll
            for (int mi = 0; mi < 4; mi++) {
                int row = o0 + wm*64 + mi*16 + g;
                float* rp0 = outb + (size_t)row*HWn;
                float* rp1 = outb + (size_t)(row + 8)*HWn;
                #pragma unroll
                for (int ni = 0; ni < 4; ni++) {
                    int col = ni*8 + 2*tig;
                    *(float2*)(rp0 + col) = make_float2(acc[mi][ni][0] + biasr[mi][0],
                                                        acc[mi][ni][1] + biasr[mi][0]);
                    *(float2*)(rp1 + col) = make_float2(acc[mi][ni][2] + biasr[mi][1],
                                                        acc[mi][ni][3] + biasr[mi][1]);
                }
            }
        }

        __syncthreads();
        cur ^= 1;
        t = tn;
    }
}

// ---------------------------------------------------------------------------
extern "C" void kernel_launch(void* const* d_in, const int* in_sizes, int n_in,
                              void* d_out, int out_size) {
    const float* x     = (const float*)d_in[0];
    const float* w_off = (const float*)d_in[1];
    const float* b_off = (const float*)d_in[2];
    const float* w_dw  = (const float*)d_in[3];
    const float* b_dw  = (const float*)d_in[4];
    const float* w_pw  = (const float*)d_in[5];
    const float* b_pw  = (const float*)d_in[6];
    float* out = (float*)d_out;

    cudaFuncSetAttribute(k1_mma, cudaFuncAttributeMaxDynamicSharedMemorySize, K1_SMEM);
    cudaFuncSetAttribute(k3_mma, cudaFuncAttributeMaxDynamicSharedMemorySize, K3_SMEM);

    k0_wk1   <<<(32*1152 + 255)/256, 256>>>(w_off);
    kT       <<<dim3(HWn/32, Cn/32, Bn), 256>>>(x);
    k1_mma   <<<dim3(Hn/2, Bn), 256, K1_SMEM>>>(x);
    k2_sample<<<dim3(Wn/16, Hn/4, Bn), 128>>>(w_dw, b_dw, b_off);
    k3_mma   <<<dim3(148, 2), 256, K3_SMEM>>>(w_pw, b_pw, out);
}

// round 13
// speedup vs baseline: 1.1955x; 1.0588x over previous
#include <cuda_runtime.h>
#include <cuda_fp16.h>
#include <cstdint>

#define Bn 4
#define Cn 128
#define Hn 128
#define Wn 128
#define On 256
#define HWn (Hn*Wn)

// Scratch (allocation-free rule: __device__ globals)
__device__ float  g_mid[Bn*HWn*Cn];     // depthwise output, [p][c], tf32-rounded
__device__ __half g_xTh[Bn*HWn*Cn];     // x transposed to [b][h][w][c], fp16
__device__ float  g_om[Bn*32*HWn];      // raw offset-conv output, 32 ch (27 used)
__device__ float  g_wk1h[32*9*128];     // offset-conv weights tf32-hi [o][tap][c]
__device__ float  g_wk1l[32*9*128];     // offset-conv weights tf32-lo

__device__ __forceinline__ uint32_t f2tf32(float f) {
    uint32_t u;
    asm("cvt.rna.tf32.f32 %0, %1;" : "=r"(u) : "f"(f));
    return u;
}

__device__ __forceinline__ void mma_tf32(float* d,
                                         uint32_t a0, uint32_t a1, uint32_t a2, uint32_t a3,
                                         uint32_t b0, uint32_t b1) {
    asm volatile(
        "mma.sync.aligned.m16n8k8.row.col.f32.tf32.tf32.f32 "
        "{%0,%1,%2,%3}, {%4,%5,%6,%7}, {%8,%9}, {%0,%1,%2,%3};"
        : "+f"(d[0]), "+f"(d[1]), "+f"(d[2]), "+f"(d[3])
        : "r"(a0), "r"(a1), "r"(a2), "r"(a3), "r"(b0), "r"(b1));
}

#define CP_ASYNC16(saddr, gptr) \
    asm volatile("cp.async.ca.shared.global [%0], [%1], 16;" \
                 :: "r"((uint32_t)(saddr)), "l"(gptr))
#define CP_COMMIT() asm volatile("cp.async.commit_group;" ::: "memory")
#define CP_WAIT0()  asm volatile("cp.async.wait_group 0;" ::: "memory")

// ---------------------------------------------------------------------------
// K0: build tf32 hi/lo split of offset-conv weights as [o pad32][tap][c].
// ---------------------------------------------------------------------------
__global__ void k0_wk1(const float* __restrict__ w_off) {
    int idx = blockIdx.x * 256 + threadIdx.x;
    if (idx >= 32*1152) return;
    int o = idx / 1152, r = idx % 1152;      // r = tap*128 + c
    int tap = r >> 7, c = r & 127;
    float v = (o < 27) ? w_off[(o*Cn + c)*9 + tap] : 0.f;
    uint32_t hi = f2tf32(v);
    g_wk1h[idx] = __uint_as_float(hi);
    g_wk1l[idx] = __uint_as_float(f2tf32(v - __uint_as_float(hi)));
}

// ---------------------------------------------------------------------------
// KT: transpose x [b][c][h][w] -> xTh [b][hw][c] fp16 (channels contiguous).
// ---------------------------------------------------------------------------
__global__ __launch_bounds__(256) void kT(const float* __restrict__ x) {
    __shared__ float t[32][33];
    int b = blockIdx.z;
    int p0 = blockIdx.x * 32, c0 = blockIdx.y * 32;
    int tx = threadIdx.x & 31, ty = threadIdx.x >> 5;  // 32 x 8
    #pragma unroll
    for (int j = 0; j < 4; j++)
        t[ty + j*8][tx] = x[((size_t)b*Cn + c0 + ty + j*8)*HWn + p0 + tx];
    __syncthreads();
    #pragma unroll
    for (int j = 0; j < 4; j++)
        g_xTh[((size_t)b*HWn + p0 + ty + j*8)*128 + c0 + tx] =
            __float2half(t[tx][ty + j*8]);
}

// ---------------------------------------------------------------------------
// K1: offset/mask conv as tf32 mma.sync GEMM with 3-MMA precision split.
// (unchanged)
// ---------------------------------------------------------------------------
#define ROWP 136
#define XSTR 552
#define AP   76
#define K1_SMEM ((16*XSTR + 64*AP) * 4)

__global__ __launch_bounds__(256) void k1_mma(const float* __restrict__ x) {
    extern __shared__ float sm[];
    float* sxh = sm;
    float* sxl = sm + 8*XSTR;
    float* sAh = sm + 16*XSTR;
    float* sAl = sAh + 32*AP;

    int tid = threadIdx.x, wid = tid >> 5, lid = tid & 31;
    int g = lid >> 2, tig = lid & 3;
    int h0 = blockIdx.x * 2, b = blockIdx.y;

    for (int i = tid; i < 16*XSTR; i += 256) sm[i] = 0.f;

    float acc[2][4][4];
    #pragma unroll
    for (int mt = 0; mt < 2; mt++)
        #pragma unroll
        for (int nt = 0; nt < 4; nt++)
            #pragma unroll
            for (int j = 0; j < 4; j++) acc[mt][nt][j] = 0.f;

    int hh  = wid >> 2;
    int wc0 = (wid & 3) * 32;

    int s_cl = tid >> 5;
    int s_r  = (tid >> 3) & 3;
    int s_q  = tid & 7;

    for (int c0 = 0; c0 < Cn; c0 += 8) {
        __syncthreads();
        {
            int row = h0 - 1 + s_r;
            bool ok = (row >= 0) && (row < Hn);
            const float* xp = x + ((size_t)b*Cn + (c0 + s_cl))*HWn + row*Wn;
            float* dh = sxh + s_cl*XSTR + s_r*ROWP + 4;
            float* dl = sxl + s_cl*XSTR + s_r*ROWP + 4;
            #pragma unroll
            for (int j = 0; j < 4; j++) {
                int col = (s_q + 8*j) * 4;
                float4 v = ok ? *(const float4*)(xp + col) : make_float4(0.f,0.f,0.f,0.f);
                uint4 vh = { f2tf32(v.x), f2tf32(v.y), f2tf32(v.z), f2tf32(v.w) };
                uint4 vl = { f2tf32(v.x - __uint_as_float(vh.x)),
                             f2tf32(v.y - __uint_as_float(vh.y)),
                             f2tf32(v.z - __uint_as_float(vh.z)),
                             f2tf32(v.w - __uint_as_float(vh.w)) };
                *(uint4*)(dh + col) = vh;
                *(uint4*)(dl + col) = vl;
            }
        }
        #pragma unroll
        for (int t = 0; t < 9; t++) {
            int i = t*256 + tid;
            int o = i / 72, k = i % 72;
            int tap = k >> 3, cl = k & 7;
            int gi = o*1152 + tap*128 + c0 + cl;
            sAh[o*AP + k] = g_wk1h[gi];
            sAl[o*AP + k] = g_wk1l[gi];
        }
        __syncthreads();

        #pragma unroll
        for (int tap = 0; tap < 9; tap++) {
            const int ty = tap / 3, tx = tap % 3;
            uint32_t ah[2][4], al[2][4];
            #pragma unroll
            for (int mt = 0; mt < 2; mt++) {
                const float* pah = sAh + (mt*16 + g)*AP + tap*8 + tig;
                const float* pal = sAl + (mt*16 + g)*AP + tap*8 + tig;
                ah[mt][0] = __float_as_uint(pah[0]);
                ah[mt][1] = __float_as_uint(pah[8*AP]);
                ah[mt][2] = __float_as_uint(pah[4]);
                ah[mt][3] = __float_as_uint(pah[8*AP + 4]);
                al[mt][0] = __float_as_uint(pal[0]);
                al[mt][1] = __float_as_uint(pal[8*AP]);
                al[mt][2] = __float_as_uint(pal[4]);
                al[mt][3] = __float_as_uint(pal[8*AP + 4]);
            }
            const float* pbh = sxh + tig*XSTR + (hh + ty)*ROWP + 3 + tx + wc0 + g;
            const float* pbl = sxl + tig*XSTR + (hh + ty)*ROWP + 3 + tx + wc0 + g;
            #pragma unroll
            for (int nt = 0; nt < 4; nt++) {
                uint32_t bh0 = __float_as_uint(pbh[nt*8]);
                uint32_t bh1 = __float_as_uint(pbh[nt*8 + 4*XSTR]);
                uint32_t bl0 = __float_as_uint(pbl[nt*8]);
                uint32_t bl1 = __float_as_uint(pbl[nt*8 + 4*XSTR]);
                #pragma unroll
                for (int mt = 0; mt < 2; mt++) {
                    mma_tf32(acc[mt][nt], ah[mt][0], ah[mt][1], ah[mt][2], ah[mt][3], bh0, bh1);
                    mma_tf32(acc[mt][nt], ah[mt][0], ah[mt][1], ah[mt][2], ah[mt][3], bl0, bl1);
                    mma_tf32(acc[mt][nt], al[mt][0], al[mt][1], al[mt][2], al[mt][3], bh0, bh1);
                }
            }
        }
    }

    float* omb = g_om + (size_t)b*32*HWn + (h0 + hh)*Wn + wc0;
    #pragma unroll
    for (int mt = 0; mt < 2; mt++) {
        int o0 = mt*16 + g;
        #pragma unroll
        for (int nt = 0; nt < 4; nt++) {
            int col = nt*8 + 2*tig;
            *(float2*)(omb + (size_t)o0*HWn + col) =
                make_float2(acc[mt][nt][0], acc[mt][nt][1]);
            *(float2*)(omb + (size_t)(o0+8)*HWn + col) =
                make_float2(acc[mt][nt][2], acc[mt][nt][3]);
        }
    }
}

// ---------------------------------------------------------------------------
// K2: bilinear gather * mask + depthwise 3x3, channel-vectorized, fp16 x.
// R12: corner blend done in half2 (HFMA2); weights kept in the tap table as
// duplicated half2. Tap accumulation stays fp32. Single pixel per iteration
// (low regs -> occupancy). mid stored pre-rounded to tf32 for k3 cp.async.
// ---------------------------------------------------------------------------
__global__ __launch_bounds__(128) void k2_sample(const float* __restrict__ w_dw,
                                                 const float* __restrict__ b_dw,
                                                 const float* __restrict__ b_off) {
    __shared__ float stap[4*16*72];     // [warp][px][tap][{idx4, wth2x4}]
    __shared__ float swdwT[9][128];     // [k][c]
    __shared__ float sbdw[128];

    int tid = threadIdx.x, wid = tid >> 5, lid = tid & 31;
    int b  = blockIdx.z;
    int w0 = blockIdx.x * 16;
    int h  = blockIdx.y * 4 + wid;      // each warp owns one row

    for (int i = tid; i < 9*128; i += 128) swdwT[i >> 7][i & 127] = w_dw[(i & 127)*9 + (i >> 7)];
    sbdw[tid] = b_dw[tid];
    __syncthreads();

    // ---- phase 1: lanes 0..15 compute tap tables for this warp's 16 px ----
    if (lid < 16) {
        int w = w0 + lid;
        const float* omb = g_om + (size_t)b*32*HWn + h*Wn + w;
        float* myt = stap + (wid*16 + lid)*72;
        #pragma unroll
        for (int k = 0; k < 9; k++) {
            float dyv = omb[(size_t)(2*k)*HWn]   + b_off[2*k];
            float dxv = omb[(size_t)(2*k+1)*HWn] + b_off[2*k+1];
            float mr  = omb[(size_t)(18+k)*HWn]  + b_off[18+k];
            float m = 1.f / (1.f + expf(-mr));
            float py = (float)(h + k/3 - 1) + dyv;
            float px = (float)(w + k%3 - 1) + dxv;
            float y0f = floorf(py), x0f = floorf(px);
            float wy = py - y0f, wx = px - x0f;
            int y0 = (int)y0f, x0 = (int)x0f;
            #pragma unroll
            for (int corner = 0; corner < 4; corner++) {
                int yy = y0 + (corner >> 1);
                int xx = x0 + (corner & 1);
                float bw = ((corner >> 1) ? wy : 1.f - wy) *
                           ((corner & 1)  ? wx : 1.f - wx);
                bool valid = (yy >= 0) && (yy < Hn) && (xx >= 0) && (xx < Wn);
                int yi = min(max(yy, 0), Hn-1);
                int xi = min(max(xx, 0), Wn-1);
                ((uint32_t*)myt)[k*8 + corner] = (uint32_t)((yi*Wn + xi) * 256);
                __half2 wh = __float2half2_rn(valid ? bw * m : 0.f);
                ((uint32_t*)myt)[k*8 + 4 + corner] = *(uint32_t*)&wh;
            }
        }
    }
    __syncwarp();

    // ---- phase 2: sweep this warp's 16 pixels ----
    const char* xTb = (const char*)g_xTh + (size_t)b*HWn*256 + lid*8;
    float* midb = g_mid + (size_t)b*HWn*128 + lid*4;
    const float* wt_base = stap + wid*16*72;
    float4 bd = *(const float4*)(sbdw + lid*4);

    for (int pi = 0; pi < 16; pi++) {
        const float* te = wt_base + pi*72;
        float a0 = bd.x, a1 = bd.y, a2 = bd.z, a3 = bd.w;
        #pragma unroll
        for (int k = 0; k < 9; k++) {
            uint4 I  = *(const uint4*)(te + k*8);        // corner byte offsets
            uint4 Wh = *(const uint4*)(te + k*8 + 4);    // duplicated half2 wts
            float4 wk = *(const float4*)(&swdwT[k][lid*4]);
            uint2 r0 = *(const uint2*)(xTb + I.x);       // LDG.64: 4 fp16 ch
            uint2 r1 = *(const uint2*)(xTb + I.y);
            uint2 r2 = *(const uint2*)(xTb + I.z);
            uint2 r3 = *(const uint2*)(xTb + I.w);
            __half2 w0 = *(__half2*)&Wh.x, w1 = *(__half2*)&Wh.y;
            __half2 w2 = *(__half2*)&Wh.z, w3 = *(__half2*)&Wh.w;
            __half2 va = __hmul2(w0, *(__half2*)&r0.x);
            va = __hfma2(w1, *(__half2*)&r1.x, va);
            va = __hfma2(w2, *(__half2*)&r2.x, va);
            va = __hfma2(w3, *(__half2*)&r3.x, va);
            __half2 vb = __hmul2(w0, *(__half2*)&r0.y);
            vb = __hfma2(w1, *(__half2*)&r1.y, vb);
            vb = __hfma2(w2, *(__half2*)&r2.y, vb);
            vb = __hfma2(w3, *(__half2*)&r3.y, vb);
            float2 fa = __half22float2(va);
            float2 fb = __half22float2(vb);
            a0 = fmaf(wk.x, fa.x, a0);
            a1 = fmaf(wk.y, fa.y, a1);
            a2 = fmaf(wk.z, fb.x, a2);
            a3 = fmaf(wk.w, fb.y, a3);
        }
        int pg = h*Wn + w0 + pi;
        uint4 u = { f2tf32(a0), f2tf32(a1), f2tf32(a2), f2tf32(a3) };
        *(uint4*)(midb + (size_t)pg*128) = u;            // tf32-rounded store
    }
}

// ---------------------------------------------------------------------------
// K3: pointwise 1x1 tf32 GEMM — persistent CTAs, cp.async B staging.
// mid is already tf32-rounded, so B needs no conversion: 16x cp.async 16B
// per thread per tile, overlapped with the 16 MMA k-steps.
// ---------------------------------------------------------------------------
#define PA 132
#define PC 132
#define NTILES (Bn*HWn/128)          // 512
#define K3_SMEM ((128*PA + 2*128*PC) * 4)

__global__ __launch_bounds__(256) void k3_mma(const float* __restrict__ w_pw,
                                              const float* __restrict__ b_pw,
                                              float* __restrict__ out) {
    extern __shared__ uint32_t smem[];
    uint32_t* sA = smem;                       // 128 o x PA
    uint32_t* sB0 = smem + 128*PA;             // 128 px x PC (buf 0)
    uint32_t* sB1 = sB0 + 128*PC;              // buf 1

    int tid = threadIdx.x;
    int wid = tid >> 5, lid = tid & 31;
    int g = lid >> 2, tig = lid & 3;
    int wm = wid >> 2, wn = wid & 3;

    int o0 = blockIdx.y * 128;

    // ---- stage A once ----
    #pragma unroll
    for (int it = 0; it < 16; it++) {
        int i = it*256 + tid;
        int m = i >> 5, q = i & 31;
        float4 v = *(const float4*)(w_pw + (size_t)(o0 + m)*Cn + q*4);
        uint4 u = { f2tf32(v.x), f2tf32(v.y), f2tf32(v.z), f2tf32(v.w) };
        *(uint4*)(sA + m*PA + q*4) = u;
    }

    float biasr[4][2];
    #pragma unroll
    for (int mi = 0; mi < 4; mi++) {
        int row = o0 + wm*64 + mi*16 + g;
        biasr[mi][0] = b_pw[row];
        biasr[mi][1] = b_pw[row + 8];
    }

    // staging map: thread covers px = (tid>>4) + j*16, q = (tid&15)*2 float4s
    int s_px = tid >> 4;
    int s_q  = (tid & 15) * 2;    // float4 index (2 per thread per px)

    uint32_t sb0_addr = (uint32_t)__cvta_generic_to_shared(sB0);
    uint32_t sb1_addr = (uint32_t)__cvta_generic_to_shared(sB1);

    // ---- prologue: stage B(tile bx) into buf0 ----
    int t = blockIdx.x;
    {
        const float* midb = g_mid + (size_t)t*128*128;
        #pragma unroll
        for (int j = 0; j < 8; j++) {
            int px = s_px + j*16;
            CP_ASYNC16(sb0_addr + (px*PC + s_q*4)*4,       midb + (size_t)px*128 + s_q*4);
            CP_ASYNC16(sb0_addr + (px*PC + (s_q+1)*4)*4,   midb + (size_t)px*128 + (s_q+1)*4);
        }
        CP_COMMIT();
        CP_WAIT0();
    }
    __syncthreads();

    int cur = 0;
    while (t < NTILES) {
        uint32_t* sB = cur ? sB1 : sB0;
        uint32_t sbn_addr = cur ? sb0_addr : sb1_addr;
        int tn = t + 148;
        bool pf = tn < NTILES;

        // ---- kick off prefetch of next tile (async, no regs) ----
        if (pf) {
            const float* midn = g_mid + (size_t)tn*128*128;
            #pragma unroll
            for (int j = 0; j < 8; j++) {
                int px = s_px + j*16;
                CP_ASYNC16(sbn_addr + (px*PC + s_q*4)*4,     midn + (size_t)px*128 + s_q*4);
                CP_ASYNC16(sbn_addr + (px*PC + (s_q+1)*4)*4, midn + (size_t)px*128 + (s_q+1)*4);
            }
            CP_COMMIT();
        }

        float acc[4][4][4];
        #pragma unroll
        for (int mi = 0; mi < 4; mi++)
            #pragma unroll
            for (int ni = 0; ni < 4; ni++)
                #pragma unroll
                for (int j = 0; j < 4; j++) acc[mi][ni][j] = 0.f;

        const uint32_t* sAr = sA + (wm*64 + g)*PA;
        const uint32_t* sBr = sB + (wn*32 + g)*PC;

        #pragma unroll
        for (int ks = 0; ks < 16; ks++) {
            int c0 = ks*8;
            uint32_t a[4][4], bf[4][2];
            #pragma unroll
            for (int mi = 0; mi < 4; mi++) {
                const uint32_t* p = sAr + mi*16*PA + c0 + tig;
                a[mi][0] = p[0]; a[mi][1] = p[8*PA]; a[mi][2] = p[4]; a[mi][3] = p[8*PA + 4];
            }
            #pragma unroll
            for (int ni = 0; ni < 4; ni++) {
                const uint32_t* p = sBr + ni*8*PC + c0 + tig;
                bf[ni][0] = p[0]; bf[ni][1] = p[4];
            }
            #pragma unroll
            for (int mi = 0; mi < 4; mi++)
                #pragma unroll
                for (int ni = 0; ni < 4; ni++)
                    mma_tf32(acc[mi][ni], a[mi][0], a[mi][1], a[mi][2], a[mi][3],
                             bf[ni][0], bf[ni][1]);
        }

        // ---- epilogue for tile t ----
        {
            int p0  = t * 128;
            int b   = p0 / HWn;
            int hw0 = p0 % HWn;
            float* outb = out + (size_t)b*On*HWn + hw0 + wn*32;
            #pragma unroll
            for (int mi = 0; mi < 4; mi++) {
                int row = o0 + wm*64 + mi*16 + g;
                float* rp0 = outb + (size_t)row*HWn;
                float* rp1 = outb + (size_t)(row + 8)*HWn;
                #pragma unroll
                for (int ni = 0; ni < 4; ni++) {
                    int col = ni*8 + 2*tig;
                    *(float2*)(rp0 + col) = make_float2(acc[mi][ni][0] + biasr[mi][0],
                                                        acc[mi][ni][1] + biasr[mi][0]);
                    *(float2*)(rp1 + col) = make_float2(acc[mi][ni][2] + biasr[mi][1],
                                                        acc[mi][ni][3] + biasr[mi][1]);
                }
            }
        }

        CP_WAIT0();
        __syncthreads();
        cur ^= 1;
        t = tn;
    }
}

// ---------------------------------------------------------------------------
extern "C" void kernel_launch(void* const* d_in, const int* in_sizes, int n_in,
                              void* d_out, int out_size) {
    const float* x     = (const float*)d_in[0];
    const float* w_off = (const float*)d_in[1];
    const float* b_off = (const float*)d_in[2];
    const float* w_dw  = (const float*)d_in[3];
    const float* b_dw  = (const float*)d_in[4];
    const float* w_pw  = (const float*)d_in[5];
    const float* b_pw  = (const float*)d_in[6];
    float* out = (float*)d_out;

    cudaFuncSetAttribute(k1_mma, cudaFuncAttributeMaxDynamicSharedMemorySize, K1_SMEM);
    cudaFuncSetAttribute(k3_mma, cudaFuncAttributeMaxDynamicSharedMemorySize, K3_SMEM);

    k0_wk1   <<<(32*1152 + 255)/256, 256>>>(w_off);
    kT       <<<dim3(HWn/32, Cn/32, Bn), 256>>>(x);
    k1_mma   <<<dim3(Hn/2, Bn), 256, K1_SMEM>>>(x);
    k2_sample<<<dim3(Wn/16, Hn/4, Bn), 128>>>(w_dw, b_dw, b_off);
    k3_mma   <<<dim3(148, 2), 256, K3_SMEM>>>(w_pw, b_pw, out);
}